// round 11
// baseline (speedup 1.0000x reference)
#include <cuda_runtime.h>
#include <cuda_fp16.h>
#include <cuda_bf16.h>
#include <cstdint>

#define T_DIM   64
#define IN_DIM  4100
#define OUT_DIM 12288
#define G_DIM   820
#define KCB     256
#define GRP     5
#define GPC     16              // groups per chunk
#define KP      128             // padded halves per chunk (16 groups * 8)
#define NCHUNK  52
#define GPAD    (NCHUNK * GPC)  // 832
#define XPADW   (NCHUNK * KP)   // 6656 halves per x row
#define WROW    136             // smem row stride in halves (272B: 16B-aligned groups, conflict-free)

// ---------------- device globals ----------------
__device__ unsigned g_xmax_bits;
__device__ unsigned g_cbmax_bits;
__device__ unsigned g_probe_sink;
__device__ __align__(16) __half g_cbtab[2 * KCB * 8];   // normalized, padded to 8
__device__ __align__(16) uint4  g_pairs[KCB * KCB];     // 1 MB pair-sum table (L2-resident)
__device__ __align__(16) __half g_xpad[T_DIM * XPADW];  // 852 KB padded-group-8 fp16 x

// ---------------- helpers ----------------
__device__ __forceinline__ float block_max_256(float m) {
    #pragma unroll
    for (int o = 16; o; o >>= 1) m = fmaxf(m, __shfl_xor_sync(0xffffffffu, m, o));
    __shared__ float sm[8];
    int lane = threadIdx.x & 31, w = threadIdx.x >> 5;
    if (!lane) sm[w] = m;
    __syncthreads();
    float r = m;
    if (!w) {
        r = (lane < 8) ? sm[lane] : 0.f;
        #pragma unroll
        for (int o = 4; o; o >>= 1) r = fmaxf(r, __shfl_xor_sync(0xffffffffu, r, o));
    }
    return r;
}
__device__ __forceinline__ uint32_t hadd2u(uint32_t a, uint32_t b) {
    uint32_t r;
    asm("add.rn.f16x2 %0, %1, %2;" : "=r"(r) : "r"(a), "r"(b));
    return r;
}

// ---- prep: block 0 = codebook dtype-detect + normalize; blocks 1..257 = x absmax
__global__ void k_prep(const float4* __restrict__ x4, const void* __restrict__ cbraw) {
    if (blockIdx.x != 0) {
        const int n4 = (T_DIM * IN_DIM) / 4;
        const int i = (blockIdx.x - 1) * 256 + threadIdx.x;
        float m = 0.f;
        if (i < n4) {
            float4 v = x4[i];
            m = fmaxf(fmaxf(fabsf(v.x), fabsf(v.y)), fmaxf(fabsf(v.z), fabsf(v.w)));
        }
        m = block_max_256(m);
        if (threadIdx.x == 0) atomicMax(&g_xmax_bits, __float_as_uint(m));
        return;
    }
    const __half*        h  = (const __half*)cbraw;
    const __nv_bfloat16* bf = (const __nv_bfloat16*)cbraw;
    const float*         f  = (const float*)cbraw;
    const int N = 2 * KCB * GRP;
    float mh = 0.f, mb = 0.f;
    for (int i = threadIdx.x; i < N; i += 256) {
        mh = fmaxf(mh, fabsf(__half2float(h[i])));
        mb = fmaxf(mb, fabsf(__bfloat162float(bf[i])));
    }
    #pragma unroll
    for (int o = 16; o; o >>= 1) {
        mh = fmaxf(mh, __shfl_xor_sync(0xffffffffu, mh, o));
        mb = fmaxf(mb, __shfl_xor_sync(0xffffffffu, mb, o));
    }
    __shared__ float smh[8], smb[8];
    __shared__ int s_dt;
    int lane = threadIdx.x & 31, w = threadIdx.x >> 5;
    if (!lane) { smh[w] = mh; smb[w] = mb; }
    __syncthreads();
    if (threadIdx.x == 0) {
        float MH = 0.f, MB = 0.f;
        #pragma unroll
        for (int i = 0; i < 8; ++i) { MH = fmaxf(MH, smh[i]); MB = fmaxf(MB, smb[i]); }
        s_dt = (MH <= 1.0f) ? 0 : ((MB <= 1.0f) ? 1 : 2);
    }
    __syncthreads();
    const int dt = s_dt;
    float m = 0.f;
    for (int i = threadIdx.x; i < N; i += 256) {
        float v = (dt == 0) ? __half2float(h[i])
                : (dt == 1) ? __bfloat162float(bf[i]) : f[i];
        m = fmaxf(m, fabsf(v));
    }
    m = block_max_256(m);
    __shared__ float s_cbm;
    if (threadIdx.x == 0) {
        g_cbmax_bits = __float_as_uint(m);
        s_cbm = fmaxf(m, 1.0f);
    }
    __syncthreads();
    const float cbm = s_cbm;
    for (int e = threadIdx.x; e < 2 * KCB; e += 256) {
        #pragma unroll
        for (int j = 0; j < 5; ++j) {
            int i = e * GRP + j;
            float v = (dt == 0) ? __half2float(h[i])
                    : (dt == 1) ? __bfloat162float(bf[i]) : f[i];
            g_cbtab[e * 8 + j] = __float2half(v / cbm);
        }
        #pragma unroll
        for (int j = 5; j < 8; ++j) g_cbtab[e * 8 + j] = __float2half(0.0f);
    }
}

// ---- mid: blocks 0..255 pair table; blocks 256..1023 x-convert (padded-8) + zero out
__global__ void k_mid(const float* __restrict__ x, float4* __restrict__ out4) {
    const int b = blockIdx.x;
    if (b < 256) {
        uint4 a = *reinterpret_cast<const uint4*>(&g_cbtab[b * 8]);
        uint4 c = *reinterpret_cast<const uint4*>(&g_cbtab[(256 + threadIdx.x) * 8]);
        uint4 u;
        u.x = hadd2u(a.x, c.x);
        u.y = hadd2u(a.y, c.y);
        u.z = hadd2u(a.z, c.z);
        u.w = 0u;
        g_pairs[b * 256 + threadIdx.x] = u;
        return;
    }
    const int j = (b - 256) * 256 + threadIdx.x;
    if (j < (T_DIM * OUT_DIM) / 4) out4[j] = make_float4(0.f, 0.f, 0.f, 0.f);
    if (j >= T_DIM * GPAD) return;
    const float xminv = 1.0f / (fmaxf(__uint_as_float(g_xmax_bits), 1.0f) * 8.0f);
    const int t = j / GPAD, g = j - t * GPAD;
    float v0 = 0.f, v1 = 0.f, v2 = 0.f, v3 = 0.f, v4 = 0.f;
    if (g < G_DIM) {
        const float* xs = x + (size_t)t * IN_DIM + g * GRP;
        v0 = xs[0] * xminv; v1 = xs[1] * xminv; v2 = xs[2] * xminv;
        v3 = xs[3] * xminv; v4 = xs[4] * xminv;
    }
    __half2 h0 = __floats2half2_rn(v0, v1);
    __half2 h1 = __floats2half2_rn(v2, v3);
    __half2 h2 = __floats2half2_rn(v4, 0.f);
    uint4 u;
    u.x = *reinterpret_cast<uint32_t*>(&h0);
    u.y = *reinterpret_cast<uint32_t*>(&h1);
    u.z = *reinterpret_cast<uint32_t*>(&h2);
    u.w = 0u;
    *reinterpret_cast<uint4*>(g_xpad + (size_t)t * XPADW + (size_t)g * 8) = u;
}

__global__ void k_probe() { g_probe_sink = 1u; }

// ---------------- PTX helpers ----------------
__device__ __forceinline__ uint32_t smem_u32(const void* p) {
    uint32_t a;
    asm("{ .reg .u64 t; cvta.to.shared.u64 t, %1; cvt.u32.u64 %0, t; }" : "=r"(a) : "l"(p));
    return a;
}
__device__ __forceinline__ void ldmx4(uint32_t& r0, uint32_t& r1, uint32_t& r2, uint32_t& r3,
                                      uint32_t addr) {
    asm volatile("ldmatrix.sync.aligned.m8n8.x4.shared.b16 {%0,%1,%2,%3}, [%4];\n"
                 : "=r"(r0), "=r"(r1), "=r"(r2), "=r"(r3) : "r"(addr));
}
__device__ __forceinline__ void mma16816(float* d, const uint32_t* a, uint32_t b0, uint32_t b1) {
    asm volatile("mma.sync.aligned.m16n8k16.row.col.f32.f16.f16.f32 "
                 "{%0,%1,%2,%3},{%4,%5,%6,%7},{%8,%9},{%0,%1,%2,%3};\n"
                 : "+f"(d[0]), "+f"(d[1]), "+f"(d[2]), "+f"(d[3])
                 : "r"(a[0]), "r"(a[1]), "r"(a[2]), "r"(a[3]), "r"(b0), "r"(b1));
}
__device__ __forceinline__ void cp16(uint32_t dst, const void* src) {
    asm volatile("cp.async.cg.shared.global [%0], [%1], 16;" :: "r"(dst), "l"(src) : "memory");
}
__device__ __forceinline__ void cp_commit() {
    asm volatile("cp.async.commit_group;" ::: "memory");
}
__device__ __forceinline__ void cp_wait0() {
    asm volatile("cp.async.wait_group 0;" ::: "memory");
}
__device__ __forceinline__ float finite_or_zero(float v) {
    unsigned b = __float_as_uint(v);
    return ((b & 0x7F800000u) == 0x7F800000u) ? 0.f : v;
}
__device__ __forceinline__ void red_add(float* p, float v) {
    asm volatile("red.global.add.f32 [%0], %1;" :: "l"(p), "f"(v) : "memory");
}

// ---------------- fused decode + GEMM ----------------
// grid 288 = 96 tiles x 3 K-splits. 512 thr: warps 0-7 MMA, 8-15 producers.
// W tile 128 x 136h (34816B) x2 | x tile 64 x 136h (17408B) x2 = 104448B smem.
#define OFF_W0  0
#define OFF_W1  34816
#define OFF_X0  69632
#define OFF_X1  87040
#define SM_BYTES 104448

__global__ void __launch_bounds__(512, 2)
k_gemm(const int* __restrict__ idx, const float* __restrict__ scales, float* __restrict__ out) {
    extern __shared__ __align__(16) char smem[];
    const uint32_t sb = smem_u32(smem);

    const int tid  = threadIdx.x;
    const int lane = tid & 31;
    const int wid  = tid >> 5;
    const int tile = blockIdx.x / 3, split = blockIdx.x - tile * 3;
    const int o0   = tile * 128;
    const int cstart = (split == 0) ? 0 : (split == 1 ? 18 : 35);
    const int L      = (split == 0) ? 18 : 17;

    const int2* idx2 = reinterpret_cast<const int2*>(idx);

    if (wid >= 8) {
        // ================= PRODUCER WARPS =================
        const int ptid = tid - 256;
        const int r  = ptid >> 4;        // 0..15 (row base; rows r, r+16, ..., r+112)
        const int gl = ptid & 15;        // group within chunk
        const size_t orow0 = (size_t)(o0 + r) * G_DIM + gl;
        const uint32_t wdst0 = sb + (uint32_t)r * (WROW * 2) + (uint32_t)gl * 16;

        auto stage_x = [&](int gc, uint32_t xoff) {
            #pragma unroll
            for (int pass = 0; pass < 4; ++pass) {
                int i = pass * 256 + ptid;          // 0..1023
                int row = i >> 4, col = i & 15;
                uint32_t dst = sb + xoff + (uint32_t)row * (WROW * 2) + (uint32_t)col * 16;
                const char* src = reinterpret_cast<const char*>(g_xpad)
                                + ((size_t)row * XPADW + (size_t)gc * KP) * 2 + (size_t)col * 16;
                cp16(dst, src);
            }
        };
        auto load_idx8 = [&](int* p, int gc) {
            int gg = gc * GPC;
            bool ok = (gg + gl < G_DIM);
            #pragma unroll
            for (int q = 0; q < 8; ++q) {
                int2 v = ok ? idx2[orow0 + (size_t)q * 16 * G_DIM + gg] : make_int2(0, 0);
                p[q] = ((v.x & 0xFF) << 8) | (v.y & 0xFF);
            }
        };
        auto decode8 = [&](const int* p, uint32_t woff) {
            const uint32_t base = wdst0 + woff;
            #pragma unroll
            for (int q = 0; q < 8; ++q)
                cp16(base + (uint32_t)q * 16 * (WROW * 2), &g_pairs[p[q]]);
        };

        int pcur[8], pnxt[8];
        load_idx8(pcur, cstart);
        stage_x(cstart, OFF_X0);
        decode8(pcur, OFF_W0);
        cp_commit();
        load_idx8(pcur, cstart + 1);
        cp_wait0();
        __syncthreads();               // buf0 ready

        for (int c = 0; c < L; ++c) {
            if (c + 1 < L) {
                stage_x(cstart + c + 1, (c & 1) ? OFF_X0 : OFF_X1);
                decode8(pcur, (c & 1) ? OFF_W0 : OFF_W1);
                cp_commit();
                if (c + 2 < L) load_idx8(pnxt, cstart + c + 2);
                cp_wait0();
                #pragma unroll
                for (int q = 0; q < 8; ++q) pcur[q] = pnxt[q];
            }
            __syncthreads();
        }
    } else {
        // ================= CONSUMER (MMA) WARPS =================
        const int mw = wid & 3;
        const int wn = wid >> 2;
        const int grp = lane >> 3, rin = lane & 7;
        const uint32_t a_row = (uint32_t)(((lane >> 3) & 1) * 8 + (lane & 7));
        const uint32_t a_k16 = (uint32_t)((lane >> 4) * 16);
        const uint32_t b_row = (uint32_t)(wn * 32 + ((grp >> 1) << 3) + rin);
        const uint32_t b_k16 = (uint32_t)((grp & 1) << 4);

        float acc[2][4][4];
        #pragma unroll
        for (int h = 0; h < 2; ++h)
            #pragma unroll
            for (int n = 0; n < 4; ++n)
                #pragma unroll
                for (int j = 0; j < 4; ++j) acc[h][n][j] = 0.f;

        __syncthreads();               // buf0 ready

        for (int c = 0; c < L; ++c) {
            const uint32_t wb = sb + ((c & 1) ? OFF_W1 : OFF_W0);
            const uint32_t xb = sb + ((c & 1) ? OFF_X1 : OFF_X0);
            #pragma unroll
            for (int ks = 0; ks < 8; ++ks) {
                const uint32_t kb = (uint32_t)ks * 32;
                uint32_t A0[4], A1[4];
                ldmx4(A0[0], A0[1], A0[2], A0[3],
                      wb + (uint32_t)(mw * 32 + a_row) * (WROW * 2) + kb + a_k16);
                ldmx4(A1[0], A1[1], A1[2], A1[3],
                      wb + (uint32_t)(mw * 32 + 16 + a_row) * (WROW * 2) + kb + a_k16);
                uint32_t b0, b1, b2, b3, b4, b5, b6, b7;
                ldmx4(b0, b1, b2, b3, xb + b_row * (WROW * 2) + kb + b_k16);
                ldmx4(b4, b5, b6, b7, xb + (b_row + 16) * (WROW * 2) + kb + b_k16);
                mma16816(acc[0][0], A0, b0, b1);
                mma16816(acc[0][1], A0, b2, b3);
                mma16816(acc[0][2], A0, b4, b5);
                mma16816(acc[0][3], A0, b6, b7);
                mma16816(acc[1][0], A1, b0, b1);
                mma16816(acc[1][1], A1, b2, b3);
                mma16816(acc[1][2], A1, b4, b5);
                mma16816(acc[1][3], A1, b6, b7);
            }
            __syncthreads();
        }

        // epilogue: scale + red.add partials
        const float xm  = fmaxf(__uint_as_float(g_xmax_bits), 1.0f) * 8.0f;
        const float cbm = fmaxf(__uint_as_float(g_cbmax_bits), 1.0f);
        const float xmcb = xm * cbm;
        #pragma unroll
        for (int h = 0; h < 2; ++h) {
            const int o  = o0 + mw * 32 + h * 16 + (lane >> 2);
            const float s  = scales[o]     * xmcb;
            const float s2 = scales[o + 8] * xmcb;
            #pragma unroll
            for (int nf = 0; nf < 4; ++nf) {
                const int t = wn * 32 + nf * 8 + ((lane & 3) << 1);
                red_add(&out[(size_t)t * OUT_DIM + o],           finite_or_zero(acc[h][nf][0] * s));
                red_add(&out[(size_t)(t + 1) * OUT_DIM + o],     finite_or_zero(acc[h][nf][1] * s));
                red_add(&out[(size_t)t * OUT_DIM + o + 8],       finite_or_zero(acc[h][nf][2] * s2));
                red_add(&out[(size_t)(t + 1) * OUT_DIM + o + 8], finite_or_zero(acc[h][nf][3] * s2));
            }
        }
    }
}

// ---------------- launcher ----------------
extern "C" void kernel_launch(void* const* d_in, const int* in_sizes, int n_in,
                              void* d_out, int out_size) {
    const float* x       = nullptr;
    const int*   indices = nullptr;
    const void*  cbooks  = nullptr;
    const float* scales  = nullptr;
    for (int i = 0; i < n_in; ++i) {
        switch (in_sizes[i]) {
            case T_DIM * IN_DIM:      x       = (const float*)d_in[i]; break;
            case OUT_DIM * G_DIM * 2: indices = (const int*)d_in[i];   break;
            case 2 * KCB * GRP:       cbooks  = d_in[i];               break;
            case OUT_DIM:             scales  = (const float*)d_in[i]; break;
        }
    }
    float* out = (float*)d_out;

    static bool attr_set = false;
    if (!attr_set) {
        cudaFuncSetAttribute(k_gemm, cudaFuncAttributeMaxDynamicSharedMemorySize, SM_BYTES);
        attr_set = true;
    }

    k_prep<<<258, 256>>>((const float4*)x, cbooks);
    k_mid<<<1024, 256>>>(x, (float4*)out);
    k_probe<<<1, 1>>>();
    k_gemm<<<96 * 3, 512, SM_BYTES>>>(indices, scales, out);
}

// round 12
// speedup vs baseline: 1.3250x; 1.3250x over previous
#include <cuda_runtime.h>
#include <cuda_fp16.h>
#include <cuda_bf16.h>
#include <cstdint>

#define T_DIM   64
#define IN_DIM  4100
#define OUT_DIM 12288
#define G_DIM   820
#define KCB     256
#define GRP     5
#define GPC     16            // groups per chunk
#define KC      80            // k halves per chunk
#define NCHUNK  52
#define KPAD    (NCHUNK * KC) // 4160
#define WROW    88            // smem row stride in halves (176B)

// ---------------- device globals ----------------
__device__ unsigned g_xmax_bits;
__device__ unsigned g_cbmax_bits;
__device__ unsigned g_probe_sink;
__device__ __align__(16) __half g_cbtab[2 * KCB * 8];  // normalized, padded to 8
__device__ __align__(16) __half g_xpad[T_DIM * KPAD];  // 532 KB fp16 x, zero-padded

// ---------------- helpers ----------------
__device__ __forceinline__ float block_max_256(float m) {
    #pragma unroll
    for (int o = 16; o; o >>= 1) m = fmaxf(m, __shfl_xor_sync(0xffffffffu, m, o));
    __shared__ float sm[8];
    int lane = threadIdx.x & 31, w = threadIdx.x >> 5;
    if (!lane) sm[w] = m;
    __syncthreads();
    float r = m;
    if (!w) {
        r = (lane < 8) ? sm[lane] : 0.f;
        #pragma unroll
        for (int o = 4; o; o >>= 1) r = fmaxf(r, __shfl_xor_sync(0xffffffffu, r, o));
    }
    return r;
}

// ---- prep: block 0 = codebook dtype-detect + normalize; blocks 1..257 = x absmax
__global__ void k_prep(const float4* __restrict__ x4, const void* __restrict__ cbraw) {
    if (blockIdx.x != 0) {
        const int n4 = (T_DIM * IN_DIM) / 4;
        const int i = (blockIdx.x - 1) * 256 + threadIdx.x;
        float m = 0.f;
        if (i < n4) {
            float4 v = x4[i];
            m = fmaxf(fmaxf(fabsf(v.x), fabsf(v.y)), fmaxf(fabsf(v.z), fabsf(v.w)));
        }
        m = block_max_256(m);
        if (threadIdx.x == 0) atomicMax(&g_xmax_bits, __float_as_uint(m));
        return;
    }
    const __half*        h  = (const __half*)cbraw;
    const __nv_bfloat16* bf = (const __nv_bfloat16*)cbraw;
    const float*         f  = (const float*)cbraw;
    const int N = 2 * KCB * GRP;
    float mh = 0.f, mb = 0.f;
    for (int i = threadIdx.x; i < N; i += 256) {
        mh = fmaxf(mh, fabsf(__half2float(h[i])));
        mb = fmaxf(mb, fabsf(__bfloat162float(bf[i])));
    }
    #pragma unroll
    for (int o = 16; o; o >>= 1) {
        mh = fmaxf(mh, __shfl_xor_sync(0xffffffffu, mh, o));
        mb = fmaxf(mb, __shfl_xor_sync(0xffffffffu, mb, o));
    }
    __shared__ float smh[8], smb[8];
    __shared__ int s_dt;
    int lane = threadIdx.x & 31, w = threadIdx.x >> 5;
    if (!lane) { smh[w] = mh; smb[w] = mb; }
    __syncthreads();
    if (threadIdx.x == 0) {
        float MH = 0.f, MB = 0.f;
        #pragma unroll
        for (int i = 0; i < 8; ++i) { MH = fmaxf(MH, smh[i]); MB = fmaxf(MB, smb[i]); }
        s_dt = (MH <= 1.0f) ? 0 : ((MB <= 1.0f) ? 1 : 2);
    }
    __syncthreads();
    const int dt = s_dt;
    float m = 0.f;
    for (int i = threadIdx.x; i < N; i += 256) {
        float v = (dt == 0) ? __half2float(h[i])
                : (dt == 1) ? __bfloat162float(bf[i]) : f[i];
        m = fmaxf(m, fabsf(v));
    }
    m = block_max_256(m);
    __shared__ float s_cbm;
    if (threadIdx.x == 0) {
        g_cbmax_bits = __float_as_uint(m);
        s_cbm = fmaxf(m, 1.0f);
    }
    __syncthreads();
    const float cbm = s_cbm;
    for (int e = threadIdx.x; e < 2 * KCB; e += 256) {
        #pragma unroll
        for (int j = 0; j < 5; ++j) {
            int i = e * GRP + j;
            float v = (dt == 0) ? __half2float(h[i])
                    : (dt == 1) ? __bfloat162float(bf[i]) : f[i];
            g_cbtab[e * 8 + j] = __float2half(v / cbm);
        }
        #pragma unroll
        for (int j = 5; j < 8; ++j) g_cbtab[e * 8 + j] = __float2half(0.0f);
    }
}

// ---- convert x (8 halves/thread, vectorized) + zero output (fold) ----
__global__ void k_convert(const float* __restrict__ x, float4* __restrict__ out4) {
    const int j = blockIdx.x * 256 + threadIdx.x;
    if (j < (T_DIM * OUT_DIM) / 4) out4[j] = make_float4(0.f, 0.f, 0.f, 0.f);
    if (j >= T_DIM * (KPAD / 8)) return;
    const float xminv = 1.0f / (fmaxf(__uint_as_float(g_xmax_bits), 1.0f) * 8.0f);
    const int t  = j / (KPAD / 8);
    const int kb = (j - t * (KPAD / 8)) * 8;
    float v[8];
    if (kb + 8 <= IN_DIM) {
        const float4* src = reinterpret_cast<const float4*>(x + (size_t)t * IN_DIM + kb);
        float4 a = src[0], b = src[1];
        v[0] = a.x; v[1] = a.y; v[2] = a.z; v[3] = a.w;
        v[4] = b.x; v[5] = b.y; v[6] = b.z; v[7] = b.w;
    } else {
        #pragma unroll
        for (int e = 0; e < 8; ++e)
            v[e] = (kb + e < IN_DIM) ? x[(size_t)t * IN_DIM + kb + e] : 0.f;
    }
    __half2 h[4];
    #pragma unroll
    for (int e = 0; e < 4; ++e)
        h[e] = __floats2half2_rn(v[2 * e] * xminv, v[2 * e + 1] * xminv);
    uint4 u;
    u.x = *reinterpret_cast<uint32_t*>(&h[0]);
    u.y = *reinterpret_cast<uint32_t*>(&h[1]);
    u.z = *reinterpret_cast<uint32_t*>(&h[2]);
    u.w = *reinterpret_cast<uint32_t*>(&h[3]);
    *reinterpret_cast<uint4*>(g_xpad + (size_t)t * KPAD + kb) = u;
}

__global__ void k_probe() { g_probe_sink = 1u; }

// ---------------- PTX helpers ----------------
__device__ __forceinline__ uint32_t smem_u32(const void* p) {
    uint32_t a;
    asm("{ .reg .u64 t; cvta.to.shared.u64 t, %1; cvt.u32.u64 %0, t; }" : "=r"(a) : "l"(p));
    return a;
}
__device__ __forceinline__ uint32_t hadd2u(uint32_t a, uint32_t b) {
    uint32_t r;
    asm("add.rn.f16x2 %0, %1, %2;" : "=r"(r) : "r"(a), "r"(b));
    return r;
}
__device__ __forceinline__ uint32_t prmt(uint32_t a, uint32_t b, uint32_t sel) {
    uint32_t r;
    asm("prmt.b32 %0, %1, %2, %3;" : "=r"(r) : "r"(a), "r"(b), "r"(sel));
    return r;
}
__device__ __forceinline__ void ldmx4(uint32_t& r0, uint32_t& r1, uint32_t& r2, uint32_t& r3,
                                      uint32_t addr) {
    asm volatile("ldmatrix.sync.aligned.m8n8.x4.shared.b16 {%0,%1,%2,%3}, [%4];\n"
                 : "=r"(r0), "=r"(r1), "=r"(r2), "=r"(r3) : "r"(addr));
}
__device__ __forceinline__ void mma16816(float* d, const uint32_t* a, uint32_t b0, uint32_t b1) {
    asm volatile("mma.sync.aligned.m16n8k16.row.col.f32.f16.f16.f32 "
                 "{%0,%1,%2,%3},{%4,%5,%6,%7},{%8,%9},{%0,%1,%2,%3};\n"
                 : "+f"(d[0]), "+f"(d[1]), "+f"(d[2]), "+f"(d[3])
                 : "r"(a[0]), "r"(a[1]), "r"(a[2]), "r"(a[3]), "r"(b0), "r"(b1));
}
__device__ __forceinline__ void sts128(uint32_t addr, uint32_t a, uint32_t b, uint32_t c, uint32_t d) {
    asm volatile("st.shared.v4.b32 [%0], {%1,%2,%3,%4};"
                 :: "r"(addr), "r"(a), "r"(b), "r"(c), "r"(d) : "memory");
}
__device__ __forceinline__ void cp16(uint32_t dst, const void* src) {
    asm volatile("cp.async.cg.shared.global [%0], [%1], 16;" :: "r"(dst), "l"(src) : "memory");
}
__device__ __forceinline__ void cp_commit() {
    asm volatile("cp.async.commit_group;" ::: "memory");
}
__device__ __forceinline__ void cp_wait0() {
    asm volatile("cp.async.wait_group 0;" ::: "memory");
}
__device__ __forceinline__ float finite_or_zero(float v) {
    unsigned b = __float_as_uint(v);
    return ((b & 0x7F800000u) == 0x7F800000u) ? 0.f : v;
}
__device__ __forceinline__ void red_add(float* p, float v) {
    asm volatile("red.global.add.f32 [%0], %1;" :: "l"(p), "f"(v) : "memory");
}

// ---------------- fused decode + GEMM, warp-specialized ----------------
// grid = 96 tiles x 3 K-splits. CTA 512 thr: warps 0-7 MMA, 8-15 producers.
// Producer thread = (row 0..127, half 0..1): decodes 8 consecutive groups (80B),
// stores via 5 aligned STS.128. W smem byte layout identical to R10.
#define OFF_W0  0
#define OFF_W1  22528
#define OFF_X0  45056
#define OFF_X1  56320
#define OFF_CB  67584
#define SM_BYTES 75776

__global__ void __launch_bounds__(512, 2)
k_gemm(const int* __restrict__ idx, const float* __restrict__ scales, float* __restrict__ out) {
    extern __shared__ __align__(16) char smem[];
    const uint32_t sb = smem_u32(smem);

    const int tid  = threadIdx.x;
    const int lane = tid & 31;
    const int wid  = tid >> 5;
    const int tile = blockIdx.x / 3, split = blockIdx.x - tile * 3;
    const int o0   = tile * 128;
    const int cstart = (split == 0) ? 0 : (split == 1 ? 18 : 35);
    const int L      = (split == 0) ? 18 : 17;

    // ---- stage codebooks ----
    {
        const uint4* src = reinterpret_cast<const uint4*>(g_cbtab);
        uint4* dst = reinterpret_cast<uint4*>(smem + OFF_CB);
        if (tid < 512) dst[tid] = src[tid];
    }
    const uint4* cbt = reinterpret_cast<const uint4*>(smem + OFF_CB);

    if (wid >= 8) {
        // ================= PRODUCER WARPS =================
        const int ptid = tid - 256;        // 0..255
        const int row  = ptid >> 1;        // 0..127
        const int half = ptid & 1;         // 0..1 (8 groups each)
        const int4* idx4 = reinterpret_cast<const int4*>(idx);
        const size_t rowbase = (size_t)(o0 + row) * G_DIM;   // in int2 units
        const uint32_t wdst0 = sb + (uint32_t)row * (WROW * 2) + (uint32_t)half * 80;

        auto stage_x = [&](int gc, uint32_t xoff) {
            #pragma unroll
            for (int pass = 0; pass < 3; ++pass) {
                int i = pass * 256 + ptid;
                if (i < 640) {
                    int xrow = i / 10, col = i - xrow * 10;
                    uint32_t dst = sb + xoff + (uint32_t)xrow * (WROW * 2) + (uint32_t)col * 16;
                    const char* src = reinterpret_cast<const char*>(g_xpad)
                                    + ((size_t)xrow * KPAD + (size_t)gc * KC) * 2 + (size_t)col * 16;
                    cp16(dst, src);
                }
            }
            cp_commit();
        };
        // load 8 groups' indices (4 contiguous LDG.128), byte-pack 2 groups/reg
        auto load_idx8 = [&](uint32_t* p, int gc) {
            const int gg = gc * GPC + half * 8;
            #pragma unroll
            for (int q = 0; q < 4; ++q) {
                int g = gg + 2 * q;
                if (g > G_DIM - 2) g = G_DIM - 2;     // tail clamp (data harmless: x=0 there)
                int4 v = __ldg(&idx4[(rowbase + (size_t)g) >> 1]);
                uint32_t t0 = prmt((uint32_t)v.x, (uint32_t)v.y, 0x0040u);
                uint32_t t1 = prmt((uint32_t)v.z, (uint32_t)v.w, 0x0040u);
                p[q] = prmt(t0, t1, 0x5410u);
            }
        };
        // decode 8 consecutive groups -> 20 packed regs -> 5 STS.128
        auto decode8 = [&](const uint32_t* p, uint32_t woff) {
            uint32_t o[20];
            #pragma unroll
            for (int pr = 0; pr < 4; ++pr) {
                uint32_t pk = p[pr];
                uint4 A0 = cbt[pk & 0xFFu];
                uint4 B0 = cbt[256 + ((pk >> 8) & 0xFFu)];
                uint4 A1 = cbt[(pk >> 16) & 0xFFu];
                uint4 B1 = cbt[256 + (pk >> 24)];
                uint32_t u0a = hadd2u(A0.x, B0.x);
                uint32_t u1a = hadd2u(A0.y, B0.y);
                uint32_t u2a = hadd2u(A0.z, B0.z);
                uint32_t u0b = hadd2u(A1.x, B1.x);
                uint32_t u1b = hadd2u(A1.y, B1.y);
                uint32_t u2b = hadd2u(A1.z, B1.z);
                o[5 * pr + 0] = u0a;
                o[5 * pr + 1] = u1a;
                o[5 * pr + 2] = prmt(u2a, u0b, 0x5410u);   // {h4a, h0b}
                o[5 * pr + 3] = prmt(u0b, u1b, 0x5432u);   // {h1b, h2b}
                o[5 * pr + 4] = prmt(u1b, u2b, 0x5432u);   // {h3b, h4b}
            }
            const uint32_t base = wdst0 + woff;
            #pragma unroll
            for (int k = 0; k < 5; ++k)
                sts128(base + (uint32_t)k * 16, o[4 * k], o[4 * k + 1], o[4 * k + 2], o[4 * k + 3]);
        };

        uint32_t pcur[4], pnxt[4];
        load_idx8(pcur, cstart);
        stage_x(cstart, OFF_X0);
        __syncthreads();               // cb ready
        decode8(pcur, OFF_W0);
        load_idx8(pcur, cstart + 1);
        cp_wait0();
        __syncthreads();               // buf0 ready

        for (int c = 0; c < L; ++c) {
            if (c + 1 < L) {
                stage_x(cstart + c + 1, (c & 1) ? OFF_X0 : OFF_X1);
                decode8(pcur, (c & 1) ? OFF_W0 : OFF_W1);
                if (c + 2 < L) load_idx8(pnxt, cstart + c + 2);
                cp_wait0();
                #pragma unroll
                for (int q = 0; q < 4; ++q) pcur[q] = pnxt[q];
            }
            __syncthreads();
        }
    } else {
        // ================= CONSUMER (MMA) WARPS =================
        const int mw = wid & 3;
        const int wn = wid >> 2;
        const int grp = lane >> 3, rin = lane & 7;
        const uint32_t a_row = (uint32_t)(((lane >> 3) & 1) * 8 + (lane & 7));
        const uint32_t a_k16 = (uint32_t)((lane >> 4) * 16);
        const uint32_t b_row = (uint32_t)(wn * 32 + ((grp >> 1) << 3) + rin);
        const uint32_t b_k16 = (uint32_t)((grp & 1) << 4);

        float acc[2][4][4];
        #pragma unroll
        for (int h = 0; h < 2; ++h)
            #pragma unroll
            for (int n = 0; n < 4; ++n)
                #pragma unroll
                for (int j = 0; j < 4; ++j) acc[h][n][j] = 0.f;

        __syncthreads();
        __syncthreads();               // buf0 ready

        for (int c = 0; c < L; ++c) {
            const uint32_t wb = sb + ((c & 1) ? OFF_W1 : OFF_W0);
            const uint32_t xb = sb + ((c & 1) ? OFF_X1 : OFF_X0);
            #pragma unroll
            for (int ks = 0; ks < 5; ++ks) {
                const uint32_t kb = (uint32_t)ks * 32;
                uint32_t A0[4], A1[4];
                ldmx4(A0[0], A0[1], A0[2], A0[3],
                      wb + (uint32_t)(mw * 32 + a_row) * (WROW * 2) + kb + a_k16);
                ldmx4(A1[0], A1[1], A1[2], A1[3],
                      wb + (uint32_t)(mw * 32 + 16 + a_row) * (WROW * 2) + kb + a_k16);
                uint32_t b0, b1, b2, b3, b4, b5, b6, b7;
                ldmx4(b0, b1, b2, b3, xb + b_row * (WROW * 2) + kb + b_k16);
                ldmx4(b4, b5, b6, b7, xb + (b_row + 16) * (WROW * 2) + kb + b_k16);
                mma16816(acc[0][0], A0, b0, b1);
                mma16816(acc[0][1], A0, b2, b3);
                mma16816(acc[0][2], A0, b4, b5);
                mma16816(acc[0][3], A0, b6, b7);
                mma16816(acc[1][0], A1, b0, b1);
                mma16816(acc[1][1], A1, b2, b3);
                mma16816(acc[1][2], A1, b4, b5);
                mma16816(acc[1][3], A1, b6, b7);
            }
            __syncthreads();
        }

        // epilogue: scale + red.add partials
        const float xm  = fmaxf(__uint_as_float(g_xmax_bits), 1.0f) * 8.0f;
        const float cbm = fmaxf(__uint_as_float(g_cbmax_bits), 1.0f);
        const float xmcb = xm * cbm;
        #pragma unroll
        for (int h = 0; h < 2; ++h) {
            const int o  = o0 + mw * 32 + h * 16 + (lane >> 2);
            const float s  = scales[o]     * xmcb;
            const float s2 = scales[o + 8] * xmcb;
            #pragma unroll
            for (int nf = 0; nf < 4; ++nf) {
                const int t = wn * 32 + nf * 8 + ((lane & 3) << 1);
                red_add(&out[(size_t)t * OUT_DIM + o],           finite_or_zero(acc[h][nf][0] * s));
                red_add(&out[(size_t)(t + 1) * OUT_DIM + o],     finite_or_zero(acc[h][nf][1] * s));
                red_add(&out[(size_t)t * OUT_DIM + o + 8],       finite_or_zero(acc[h][nf][2] * s2));
                red_add(&out[(size_t)(t + 1) * OUT_DIM + o + 8], finite_or_zero(acc[h][nf][3] * s2));
            }
        }
    }
}

// ---------------- launcher ----------------
extern "C" void kernel_launch(void* const* d_in, const int* in_sizes, int n_in,
                              void* d_out, int out_size) {
    const float* x       = nullptr;
    const int*   indices = nullptr;
    const void*  cbooks  = nullptr;
    const float* scales  = nullptr;
    for (int i = 0; i < n_in; ++i) {
        switch (in_sizes[i]) {
            case T_DIM * IN_DIM:      x       = (const float*)d_in[i]; break;
            case OUT_DIM * G_DIM * 2: indices = (const int*)d_in[i];   break;
            case 2 * KCB * GRP:       cbooks  = d_in[i];               break;
            case OUT_DIM:             scales  = (const float*)d_in[i]; break;
        }
    }
    float* out = (float*)d_out;

    static bool attr_set = false;
    if (!attr_set) {
        cudaFuncSetAttribute(k_gemm, cudaFuncAttributeMaxDynamicSharedMemorySize, SM_BYTES);
        attr_set = true;
    }

    k_prep<<<258, 256>>>((const float4*)x, cbooks);
    k_convert<<<768, 256>>>(x, (float4*)out);
    k_probe<<<1, 1>>>();
    k_gemm<<<96 * 3, 512, SM_BYTES>>>(indices, scales, out);
}

// round 13
// speedup vs baseline: 1.3969x; 1.0543x over previous
#include <cuda_runtime.h>
#include <cuda_fp16.h>
#include <cuda_bf16.h>
#include <cstdint>

#define T_DIM   64
#define IN_DIM  4100
#define OUT_DIM 12288
#define G_DIM   820
#define KCB     256
#define GRP     5
#define GPC     16            // groups per chunk
#define KC      80            // k halves per chunk
#define NCHUNK  52
#define KPAD    (NCHUNK * KC) // 4160
#define WROW    88            // smem row stride in halves (176B)

// ---------------- device globals ----------------
__device__ unsigned g_xmax_bits;
__device__ unsigned g_cbmax_bits;
__device__ unsigned g_probe_sink;
__device__ __align__(16) __half g_cbtab[2 * KCB * 8];  // normalized, padded to 8
__device__ __align__(16) __half g_xpad[T_DIM * KPAD];  // 532 KB fp16 x, zero-padded

// ---------------- helpers ----------------
__device__ __forceinline__ float block_max_256(float m) {
    #pragma unroll
    for (int o = 16; o; o >>= 1) m = fmaxf(m, __shfl_xor_sync(0xffffffffu, m, o));
    __shared__ float sm[8];
    int lane = threadIdx.x & 31, w = threadIdx.x >> 5;
    if (!lane) sm[w] = m;
    __syncthreads();
    float r = m;
    if (!w) {
        r = (lane < 8) ? sm[lane] : 0.f;
        #pragma unroll
        for (int o = 4; o; o >>= 1) r = fmaxf(r, __shfl_xor_sync(0xffffffffu, r, o));
    }
    return r;
}

// ---- prep: block 0 = codebook dtype-detect + normalize; blocks 1..257 = x absmax
__global__ void k_prep(const float4* __restrict__ x4, const void* __restrict__ cbraw) {
    if (blockIdx.x != 0) {
        const int n4 = (T_DIM * IN_DIM) / 4;
        const int i = (blockIdx.x - 1) * 256 + threadIdx.x;
        float m = 0.f;
        if (i < n4) {
            float4 v = x4[i];
            m = fmaxf(fmaxf(fabsf(v.x), fabsf(v.y)), fmaxf(fabsf(v.z), fabsf(v.w)));
        }
        m = block_max_256(m);
        if (threadIdx.x == 0) atomicMax(&g_xmax_bits, __float_as_uint(m));
        return;
    }
    const __half*        h  = (const __half*)cbraw;
    const __nv_bfloat16* bf = (const __nv_bfloat16*)cbraw;
    const float*         f  = (const float*)cbraw;
    const int N = 2 * KCB * GRP;
    float mh = 0.f, mb = 0.f;
    for (int i = threadIdx.x; i < N; i += 256) {
        mh = fmaxf(mh, fabsf(__half2float(h[i])));
        mb = fmaxf(mb, fabsf(__bfloat162float(bf[i])));
    }
    #pragma unroll
    for (int o = 16; o; o >>= 1) {
        mh = fmaxf(mh, __shfl_xor_sync(0xffffffffu, mh, o));
        mb = fmaxf(mb, __shfl_xor_sync(0xffffffffu, mb, o));
    }
    __shared__ float smh[8], smb[8];
    __shared__ int s_dt;
    int lane = threadIdx.x & 31, w = threadIdx.x >> 5;
    if (!lane) { smh[w] = mh; smb[w] = mb; }
    __syncthreads();
    if (threadIdx.x == 0) {
        float MH = 0.f, MB = 0.f;
        #pragma unroll
        for (int i = 0; i < 8; ++i) { MH = fmaxf(MH, smh[i]); MB = fmaxf(MB, smb[i]); }
        s_dt = (MH <= 1.0f) ? 0 : ((MB <= 1.0f) ? 1 : 2);
    }
    __syncthreads();
    const int dt = s_dt;
    float m = 0.f;
    for (int i = threadIdx.x; i < N; i += 256) {
        float v = (dt == 0) ? __half2float(h[i])
                : (dt == 1) ? __bfloat162float(bf[i]) : f[i];
        m = fmaxf(m, fabsf(v));
    }
    m = block_max_256(m);
    __shared__ float s_cbm;
    if (threadIdx.x == 0) {
        g_cbmax_bits = __float_as_uint(m);
        s_cbm = fmaxf(m, 1.0f);
    }
    __syncthreads();
    const float cbm = s_cbm;
    for (int e = threadIdx.x; e < 2 * KCB; e += 256) {
        #pragma unroll
        for (int j = 0; j < 5; ++j) {
            int i = e * GRP + j;
            float v = (dt == 0) ? __half2float(h[i])
                    : (dt == 1) ? __bfloat162float(bf[i]) : f[i];
            g_cbtab[e * 8 + j] = __float2half(v / cbm);
        }
        #pragma unroll
        for (int j = 5; j < 8; ++j) g_cbtab[e * 8 + j] = __float2half(0.0f);
    }
}

// ---- convert x (8 halves/thread, vectorized) + zero output (fold) ----
__global__ void k_convert(const float* __restrict__ x, float4* __restrict__ out4) {
    const int j = blockIdx.x * 256 + threadIdx.x;
    if (j < (T_DIM * OUT_DIM) / 4) out4[j] = make_float4(0.f, 0.f, 0.f, 0.f);
    if (j >= T_DIM * (KPAD / 8)) return;
    const float xminv = 1.0f / (fmaxf(__uint_as_float(g_xmax_bits), 1.0f) * 8.0f);
    const int t  = j / (KPAD / 8);
    const int kb = (j - t * (KPAD / 8)) * 8;
    float v[8];
    if (kb + 8 <= IN_DIM) {
        const float4* src = reinterpret_cast<const float4*>(x + (size_t)t * IN_DIM + kb);
        float4 a = src[0], b = src[1];
        v[0] = a.x; v[1] = a.y; v[2] = a.z; v[3] = a.w;
        v[4] = b.x; v[5] = b.y; v[6] = b.z; v[7] = b.w;
    } else {
        #pragma unroll
        for (int e = 0; e < 8; ++e)
            v[e] = (kb + e < IN_DIM) ? x[(size_t)t * IN_DIM + kb + e] : 0.f;
    }
    __half2 h[4];
    #pragma unroll
    for (int e = 0; e < 4; ++e)
        h[e] = __floats2half2_rn(v[2 * e] * xminv, v[2 * e + 1] * xminv);
    uint4 u;
    u.x = *reinterpret_cast<uint32_t*>(&h[0]);
    u.y = *reinterpret_cast<uint32_t*>(&h[1]);
    u.z = *reinterpret_cast<uint32_t*>(&h[2]);
    u.w = *reinterpret_cast<uint32_t*>(&h[3]);
    *reinterpret_cast<uint4*>(g_xpad + (size_t)t * KPAD + kb) = u;
}

__global__ void k_probe() { g_probe_sink = 1u; }

// ---------------- PTX helpers ----------------
__device__ __forceinline__ uint32_t smem_u32(const void* p) {
    uint32_t a;
    asm("{ .reg .u64 t; cvta.to.shared.u64 t, %1; cvt.u32.u64 %0, t; }" : "=r"(a) : "l"(p));
    return a;
}
__device__ __forceinline__ uint32_t hadd2u(uint32_t a, uint32_t b) {
    uint32_t r;
    asm("add.rn.f16x2 %0, %1, %2;" : "=r"(r) : "r"(a), "r"(b));
    return r;
}
__device__ __forceinline__ void ldmx4(uint32_t& r0, uint32_t& r1, uint32_t& r2, uint32_t& r3,
                                      uint32_t addr) {
    asm volatile("ldmatrix.sync.aligned.m8n8.x4.shared.b16 {%0,%1,%2,%3}, [%4];\n"
                 : "=r"(r0), "=r"(r1), "=r"(r2), "=r"(r3) : "r"(addr));
}
__device__ __forceinline__ void mma16816(float* d, const uint32_t* a, uint32_t b0, uint32_t b1) {
    asm volatile("mma.sync.aligned.m16n8k16.row.col.f32.f16.f16.f32 "
                 "{%0,%1,%2,%3},{%4,%5,%6,%7},{%8,%9},{%0,%1,%2,%3};\n"
                 : "+f"(d[0]), "+f"(d[1]), "+f"(d[2]), "+f"(d[3])
                 : "r"(a[0]), "r"(a[1]), "r"(a[2]), "r"(a[3]), "r"(b0), "r"(b1));
}
__device__ __forceinline__ void cp16(uint32_t dst, const void* src) {
    asm volatile("cp.async.cg.shared.global [%0], [%1], 16;" :: "r"(dst), "l"(src) : "memory");
}
__device__ __forceinline__ void cp_commit() {
    asm volatile("cp.async.commit_group;" ::: "memory");
}
__device__ __forceinline__ void cp_wait0() {
    asm volatile("cp.async.wait_group 0;" ::: "memory");
}
__device__ __forceinline__ float finite_or_zero(float v) {
    unsigned b = __float_as_uint(v);
    return ((b & 0x7F800000u) == 0x7F800000u) ? 0.f : v;
}
__device__ __forceinline__ void red_add(float* p, float v) {
    asm volatile("red.global.add.f32 [%0], %1;" :: "l"(p), "f"(v) : "memory");
}

// ---------------- fused decode + GEMM, warp-specialized ----------------
// grid = 96 tiles x 3 K-splits. CTA 512 thr: warps 0-7 MMA, 8-15 producers.
// Codebook staged 2x (16 KB): lanes 0-15 gather from copy 0, lanes 16-31 from
// copy 1 -> cross-half bank collisions impossible on the random gathers.
#define OFF_W0  0
#define OFF_W1  22528
#define OFF_X0  45056
#define OFF_X1  56320
#define OFF_CB  67584
#define SM_BYTES 83968

__device__ __forceinline__ void store_group(char* p, uint32_t u0, uint32_t u1, uint32_t u2,
                                            bool odd) {
    if (odd) {
        *reinterpret_cast<unsigned short*>(p)     = (unsigned short)(u0 & 0xFFFFu);
        *reinterpret_cast<uint32_t*>(p + 2)       = (u0 >> 16) | (u1 << 16);
        *reinterpret_cast<uint32_t*>(p + 6)       = (u1 >> 16) | (u2 << 16);
    } else {
        *reinterpret_cast<uint32_t*>(p)           = u0;
        *reinterpret_cast<uint32_t*>(p + 4)       = u1;
        *reinterpret_cast<unsigned short*>(p + 8) = (unsigned short)(u2 & 0xFFFFu);
    }
}

__global__ void __launch_bounds__(512, 2)
k_gemm(const int* __restrict__ idx, const float* __restrict__ scales, float* __restrict__ out) {
    extern __shared__ __align__(16) char smem[];
    const uint32_t sb = smem_u32(smem);

    const int tid  = threadIdx.x;
    const int lane = tid & 31;
    const int wid  = tid >> 5;
    const int tile = blockIdx.x / 3, split = blockIdx.x - tile * 3;
    const int o0   = tile * 128;
    const int cstart = (split == 0) ? 0 : (split == 1 ? 18 : 35);
    const int L      = (split == 0) ? 18 : 17;

    // ---- stage codebooks, 2 replicas ----
    {
        const uint4* src = reinterpret_cast<const uint4*>(g_cbtab);
        uint4* dst = reinterpret_cast<uint4*>(smem + OFF_CB);
        #pragma unroll
        for (int i = tid; i < 1024; i += 512) dst[i] = src[i & 511];
    }
    const int2* idx2 = reinterpret_cast<const int2*>(idx);

    if (wid >= 8) {
        // ================= PRODUCER WARPS =================
        const int ptid = tid - 256;
        const int r  = ptid >> 4;
        const int gl = ptid & 15;
        const bool odd = (gl & 1);
        const size_t orow0 = (size_t)(o0 + r) * G_DIM + gl;
        char* const wrow_base0 = smem + (size_t)r * (WROW * 2) + gl * 10;
        // half-warp replica selection: lanes 0-15 -> copy 0, 16-31 -> copy 1
        const uint4* cbt = reinterpret_cast<const uint4*>(smem + OFF_CB)
                         + ((lane >> 4) & 1) * 512;

        auto stage_x = [&](int gc, uint32_t xoff) {
            #pragma unroll
            for (int pass = 0; pass < 3; ++pass) {
                int i = pass * 256 + ptid;
                if (i < 640) {
                    int row = i / 10, col = i - row * 10;
                    uint32_t dst = sb + xoff + (uint32_t)row * (WROW * 2) + (uint32_t)col * 16;
                    const char* src = reinterpret_cast<const char*>(g_xpad)
                                    + ((size_t)row * KPAD + (size_t)gc * KC) * 2 + (size_t)col * 16;
                    cp16(dst, src);
                }
            }
            cp_commit();
        };
        auto load_idx8 = [&](int2* p, int gc) {
            int gg = gc * GPC;
            bool ok = (gg + gl < G_DIM);
            #pragma unroll
            for (int q = 0; q < 8; ++q)
                p[q] = ok ? idx2[orow0 + (size_t)q * 16 * G_DIM + gg] : make_int2(0, 0);
        };
        // decode with 2-group load batching (4-deep LDS MLP)
        auto decode8 = [&](const int2* p, uint32_t woff) {
            char* base = wrow_base0 + woff;
            #pragma unroll
            for (int q = 0; q < 8; q += 2) {
                uint4 a0 = cbt[p[q].x & 0xFF];
                uint4 b0 = cbt[256 + (p[q].y & 0xFF)];
                uint4 a1 = cbt[p[q + 1].x & 0xFF];
                uint4 b1 = cbt[256 + (p[q + 1].y & 0xFF)];
                store_group(base + (size_t)q * 16 * (WROW * 2),
                            hadd2u(a0.x, b0.x), hadd2u(a0.y, b0.y), hadd2u(a0.z, b0.z), odd);
                store_group(base + (size_t)(q + 1) * 16 * (WROW * 2),
                            hadd2u(a1.x, b1.x), hadd2u(a1.y, b1.y), hadd2u(a1.z, b1.z), odd);
            }
        };

        int2 pcur[8], pnxt[8];
        load_idx8(pcur, cstart);
        stage_x(cstart, OFF_X0);
        __syncthreads();               // cb ready
        decode8(pcur, OFF_W0);
        load_idx8(pcur, cstart + 1);
        cp_wait0();
        __syncthreads();               // buf0 ready

        for (int c = 0; c < L; ++c) {
            if (c + 1 < L) {
                stage_x(cstart + c + 1, (c & 1) ? OFF_X0 : OFF_X1);
                decode8(pcur, (c & 1) ? OFF_W0 : OFF_W1);
                if (c + 2 < L) load_idx8(pnxt, cstart + c + 2);
                cp_wait0();
                #pragma unroll
                for (int q = 0; q < 8; ++q) pcur[q] = pnxt[q];
            }
            __syncthreads();
        }
    } else {
        // ================= CONSUMER (MMA) WARPS =================
        const int mw = wid & 3;
        const int wn = wid >> 2;
        const int grp = lane >> 3, rin = lane & 7;
        const uint32_t a_row = (uint32_t)(((lane >> 3) & 1) * 8 + (lane & 7));
        const uint32_t a_k16 = (uint32_t)((lane >> 4) * 16);
        const uint32_t b_row = (uint32_t)(wn * 32 + ((grp >> 1) << 3) + rin);
        const uint32_t b_k16 = (uint32_t)((grp & 1) << 4);

        float acc[2][4][4];
        #pragma unroll
        for (int h = 0; h < 2; ++h)
            #pragma unroll
            for (int n = 0; n < 4; ++n)
                #pragma unroll
                for (int j = 0; j < 4; ++j) acc[h][n][j] = 0.f;

        __syncthreads();
        __syncthreads();               // buf0 ready

        for (int c = 0; c < L; ++c) {
            const uint32_t wb = sb + ((c & 1) ? OFF_W1 : OFF_W0);
            const uint32_t xb = sb + ((c & 1) ? OFF_X1 : OFF_X0);
            #pragma unroll
            for (int ks = 0; ks < 5; ++ks) {
                const uint32_t kb = (uint32_t)ks * 32;
                uint32_t A0[4], A1[4];
                ldmx4(A0[0], A0[1], A0[2], A0[3],
                      wb + (uint32_t)(mw * 32 + a_row) * (WROW * 2) + kb + a_k16);
                ldmx4(A1[0], A1[1], A1[2], A1[3],
                      wb + (uint32_t)(mw * 32 + 16 + a_row) * (WROW * 2) + kb + a_k16);
                uint32_t b0, b1, b2, b3, b4, b5, b6, b7;
                ldmx4(b0, b1, b2, b3, xb + b_row * (WROW * 2) + kb + b_k16);
                ldmx4(b4, b5, b6, b7, xb + (b_row + 16) * (WROW * 2) + kb + b_k16);
                mma16816(acc[0][0], A0, b0, b1);
                mma16816(acc[0][1], A0, b2, b3);
                mma16816(acc[0][2], A0, b4, b5);
                mma16816(acc[0][3], A0, b6, b7);
                mma16816(acc[1][0], A1, b0, b1);
                mma16816(acc[1][1], A1, b2, b3);
                mma16816(acc[1][2], A1, b4, b5);
                mma16816(acc[1][3], A1, b6, b7);
            }
            __syncthreads();
        }

        // epilogue: scale + red.add partials
        const float xm  = fmaxf(__uint_as_float(g_xmax_bits), 1.0f) * 8.0f;
        const float cbm = fmaxf(__uint_as_float(g_cbmax_bits), 1.0f);
        const float xmcb = xm * cbm;
        #pragma unroll
        for (int h = 0; h < 2; ++h) {
            const int o  = o0 + mw * 32 + h * 16 + (lane >> 2);
            const float s  = scales[o]     * xmcb;
            const float s2 = scales[o + 8] * xmcb;
            #pragma unroll
            for (int nf = 0; nf < 4; ++nf) {
                const int t = wn * 32 + nf * 8 + ((lane & 3) << 1);
                red_add(&out[(size_t)t * OUT_DIM + o],           finite_or_zero(acc[h][nf][0] * s));
                red_add(&out[(size_t)(t + 1) * OUT_DIM + o],     finite_or_zero(acc[h][nf][1] * s));
                red_add(&out[(size_t)t * OUT_DIM + o + 8],       finite_or_zero(acc[h][nf][2] * s2));
                red_add(&out[(size_t)(t + 1) * OUT_DIM + o + 8], finite_or_zero(acc[h][nf][3] * s2));
            }
        }
    }
}

// ---------------- launcher ----------------
extern "C" void kernel_launch(void* const* d_in, const int* in_sizes, int n_in,
                              void* d_out, int out_size) {
    const float* x       = nullptr;
    const int*   indices = nullptr;
    const void*  cbooks  = nullptr;
    const float* scales  = nullptr;
    for (int i = 0; i < n_in; ++i) {
        switch (in_sizes[i]) {
            case T_DIM * IN_DIM:      x       = (const float*)d_in[i]; break;
            case OUT_DIM * G_DIM * 2: indices = (const int*)d_in[i];   break;
            case 2 * KCB * GRP:       cbooks  = d_in[i];               break;
            case OUT_DIM:             scales  = (const float*)d_in[i]; break;
        }
    }
    float* out = (float*)d_out;

    static bool attr_set = false;
    if (!attr_set) {
        cudaFuncSetAttribute(k_gemm, cudaFuncAttributeMaxDynamicSharedMemorySize, SM_BYTES);
        attr_set = true;
    }

    k_prep<<<258, 256>>>((const float4*)x, cbooks);
    k_convert<<<768, 256>>>(x, (float4*)out);
    k_probe<<<1, 1>>>();
    k_gemm<<<96 * 3, 512, SM_BYTES>>>(indices, scales, out);
}